// round 6
// baseline (speedup 1.0000x reference)
#include <cuda_runtime.h>
#include <cuda_bf16.h>
#include <cstdint>

// ---------------- problem constants ----------------
#define B_ROWS 1024
#define D_DIM  512
#define C_CLS  100000
#define S_SCALE 64.0f
#define M_MARG  0.5f
#define EPS_A   1e-07f

// GEMM tiling: per-CTA 128 rows x 128 classes, K chunked by 64 (bf16), 3-stage pipeline
#define BM 128
#define BN 128
#define BK 64
#define ROW_BYTES   144                        // 64 bf16 = 128B data + 16B pad
#define TILE_BYTES  (128 * ROW_BYTES)          // 18432
#define STAGE_BYTES (2 * TILE_BYTES)           // X + W
#define NSTAGE 3
#define SMEM_BYTES  (NSTAGE * STAGE_BYTES + 256)

// ---------------- scratch ----------------
__device__ float          g_xn[B_ROWS * D_DIM];          // normalized features fp32
__device__ __nv_bfloat16  g_xbf[B_ROWS * D_DIM];         // normalized features bf16
__device__ __nv_bfloat16  g_wbf[(size_t)C_CLS * D_DIM];  // W in bf16
__device__ float          g_rowsum[B_ROWS];
__device__ float          g_tgt[B_ROWS];
__device__ int            g_y_is64;

// ---------------- helpers ----------------
__device__ __forceinline__ void ldsm_x4(unsigned r[4], unsigned addr) {
    asm volatile("ldmatrix.sync.aligned.m8n8.x4.shared.b16 {%0,%1,%2,%3}, [%4];"
                 : "=r"(r[0]), "=r"(r[1]), "=r"(r[2]), "=r"(r[3]) : "r"(addr));
}

__device__ __forceinline__ void mma_bf16(float c[4], const unsigned a[4], const unsigned b[2]) {
    asm volatile(
        "mma.sync.aligned.m16n8k16.row.col.f32.bf16.bf16.f32 "
        "{%0,%1,%2,%3},{%4,%5,%6,%7},{%8,%9},{%0,%1,%2,%3};"
        : "+f"(c[0]), "+f"(c[1]), "+f"(c[2]), "+f"(c[3])
        : "r"(a[0]), "r"(a[1]), "r"(a[2]), "r"(a[3]),
          "r"(b[0]), "r"(b[1]));
}

__device__ __forceinline__ void cp16(unsigned dst, const void* src, bool valid) {
    int sz = valid ? 16 : 0;
    asm volatile("cp.async.cg.shared.global [%0], [%1], 16, %2;\n"
                 :: "r"(dst), "l"(src), "r"(sz));
}
__device__ __forceinline__ void cp_commit() {
    asm volatile("cp.async.commit_group;\n" ::: "memory");
}
__device__ __forceinline__ void cp_wait1() {
    asm volatile("cp.async.wait_group 1;\n" ::: "memory");
}
__device__ __forceinline__ void cp_wait0() {
    asm volatile("cp.async.wait_group 0;\n" ::: "memory");
}

// ---------------- kernel 0: detect y_true dtype ----------------
__global__ void detect_kernel(const int* __restrict__ y32) {
    int all_zero = 1;
    #pragma unroll
    for (int i = 0; i < 16; i++)
        if (y32[2 * i + 1] != 0) all_zero = 0;
    g_y_is64 = all_zero;
}

// ---------------- kernel 0b: convert W to bf16 ----------------
__global__ __launch_bounds__(256) void wconv_kernel(const float* __restrict__ W) {
    size_t i = ((size_t)blockIdx.x * 256 + threadIdx.x) * 4;   // 50000*256*4 = 51.2e6 exact
    float4 v = *(const float4*)(W + i);
    __nv_bfloat162 lo = __floats2bfloat162_rn(v.x, v.y);
    __nv_bfloat162 hi = __floats2bfloat162_rn(v.z, v.w);
    __nv_bfloat162* dst = (__nv_bfloat162*)(g_wbf + i);
    dst[0] = lo;
    dst[1] = hi;
}

// ---------------- kernel 1: L2-normalize rows (fp32 + bf16), zero rowsum ----------------
__global__ __launch_bounds__(128) void norm_kernel(const float* __restrict__ X) {
    int b = blockIdx.x;
    const float* xr = X + (size_t)b * D_DIM;
    float s = 0.f;
    #pragma unroll
    for (int i = threadIdx.x; i < D_DIM; i += 128) {
        float v = xr[i];
        s += v * v;
    }
    #pragma unroll
    for (int o = 16; o > 0; o >>= 1) s += __shfl_xor_sync(0xffffffffu, s, o);
    __shared__ float red[4];
    int w = threadIdx.x >> 5;
    if ((threadIdx.x & 31) == 0) red[w] = s;
    __syncthreads();
    float tot = red[0] + red[1] + red[2] + red[3];
    float inv = 1.0f / fmaxf(sqrtf(tot), 1e-12f);
    #pragma unroll
    for (int i = threadIdx.x; i < D_DIM; i += 128) {
        float v = xr[i] * inv;
        g_xn[(size_t)b * D_DIM + i] = v;
        g_xbf[(size_t)b * D_DIM + i] = __float2bfloat16_rn(v);
    }
    if (threadIdx.x == 0) g_rowsum[b] = 0.f;
}

// ---------------- kernel 2: fp32 true-class logit ----------------
__global__ __launch_bounds__(128) void tgt_kernel(const float* __restrict__ W,
                                                  const void* __restrict__ y) {
    int b = blockIdx.x;
    long long c;
    if (g_y_is64) c = ((const long long*)y)[b];
    else          c = (long long)((const int*)y)[b];
    if (c < 0) c = 0;
    if (c >= C_CLS) c = C_CLS - 1;
    const float* xr = g_xn + (size_t)b * D_DIM;
    const float* wr = W + (size_t)c * D_DIM;
    float s = 0.f;
    #pragma unroll
    for (int i = threadIdx.x; i < D_DIM; i += 128) s += xr[i] * wr[i];
    #pragma unroll
    for (int o = 16; o > 0; o >>= 1) s += __shfl_xor_sync(0xffffffffu, s, o);
    __shared__ float red[4];
    int w = threadIdx.x >> 5;
    if ((threadIdx.x & 31) == 0) red[w] = s;
    __syncthreads();
    if (threadIdx.x == 0) g_tgt[b] = red[0] + red[1] + red[2] + red[3];
}

// ---------------- kernel 3: fused bf16 GEMM + exp + row-sum ----------------
// 512 threads, 16 warps in a 4(M) x 4(N) grid; per-warp tile 32x32.
// 3-stage cp.async pipeline (wait_group 1 -> two loads in flight).
__global__ __launch_bounds__(512, 2) void gemm_exp_kernel() {
    extern __shared__ char sm_raw[];

    const int tid  = threadIdx.x;
    const int lane = tid & 31;
    const int warp = tid >> 5;     // 0..15
    const int warpM = warp & 3;    // 4 warps over M (32 rows each)
    const int warpN = warp >> 2;   // 4 warps over N (32 cols each)
    const int colbase = blockIdx.x * BN;

    unsigned sbase = (unsigned)__cvta_generic_to_shared(sm_raw);
    sbase = (sbase + 255u) & ~255u;

    // loader mapping: 512 threads, each owns 1 row (X) + 1 row (W), 2 x 16B segs each
    const int lr   = tid >> 2;           // 0..127 row
    const int seg0 = (tid & 3);          // segments seg0 and seg0+4 (of 8 per 128B row)

    const int wc = colbase + lr;         // class index for the W row this thread loads
    const bool wvalid = (wc < C_CLS);
    const __nv_bfloat16* wrow = g_wbf + (size_t)(wvalid ? wc : 0) * D_DIM + seg0 * 8;

    auto load_chunk = [&](int g, int st) {
        const int rt = g >> 3, kt = g & 7;
        const unsigned xs = sbase + (unsigned)st * (unsigned)STAGE_BYTES;
        const unsigned ws = xs + (unsigned)TILE_BYTES;
        const __nv_bfloat16* xb =
            g_xbf + (size_t)(rt * BM + lr) * D_DIM + kt * BK + seg0 * 8;
        const unsigned off0 = (unsigned)(lr * ROW_BYTES + seg0 * 16);
        cp16(xs + off0,      xb,           true);
        cp16(xs + off0 + 64, xb + 32,      true);
        cp16(ws + off0,      wrow + kt * BK,      wvalid);
        cp16(ws + off0 + 64, wrow + kt * BK + 32, wvalid);
    };

    const int lrow = lane & 15;
    const int lhi  = (lane >> 4) * 16;
    const int qrow = lane >> 2;
    const int qcol = lane & 3;

    // prologue: 2 chunks in flight
    load_chunk(0, 0);
    cp_commit();
    load_chunk(1, 1);
    cp_commit();

    float acc[2][4][4];
    #pragma unroll
    for (int mi = 0; mi < 2; mi++)
        #pragma unroll
        for (int ni = 0; ni < 4; ni++)
            #pragma unroll
            for (int r = 0; r < 4; r++) acc[mi][ni][r] = 0.f;

    for (int g = 0; g < 64; g++) {
        const int s = g % NSTAGE;

        if (g + 2 < 64) cp_wait1();   // chunk g landed; g+1 may still fly
        else            cp_wait0();   // tail: drain everything
        __syncthreads();

        if (g + 2 < 64) {
            load_chunk(g + 2, (g + 2) % NSTAGE);
            cp_commit();
        }

        const unsigned xs = sbase + (unsigned)s * (unsigned)STAGE_BYTES;
        const unsigned ws = xs + (unsigned)TILE_BYTES;

        #pragma unroll
        for (int ks = 0; ks < 4; ks++) {
            const int kb = ks * 32;   // k16 step = 32 bytes
            unsigned a[2][4];
            unsigned bq[2][4];
            #pragma unroll
            for (int mi = 0; mi < 2; mi++)
                ldsm_x4(a[mi], xs + (unsigned)((warpM * 32 + mi * 16 + lrow) * ROW_BYTES + kb + lhi));
            #pragma unroll
            for (int p = 0; p < 2; p++)
                ldsm_x4(bq[p], ws + (unsigned)((warpN * 32 + p * 16 + lrow) * ROW_BYTES + kb + lhi));
            #pragma unroll
            for (int mi = 0; mi < 2; mi++) {
                #pragma unroll
                for (int p = 0; p < 2; p++) {
                    unsigned b0[2] = { bq[p][0], bq[p][2] };
                    unsigned b1[2] = { bq[p][1], bq[p][3] };
                    mma_bf16(acc[mi][2 * p + 0], a[mi], b0);
                    mma_bf16(acc[mi][2 * p + 1], a[mi], b1);
                }
            }
        }

        if ((g & 7) == 7) {
            const int rt = g >> 3;
            #pragma unroll
            for (int mi = 0; mi < 2; mi++) {
                int r0 = rt * BM + warpM * 32 + mi * 16 + qrow;
                int r1 = r0 + 8;
                float s0 = 0.f, s1 = 0.f;
                #pragma unroll
                for (int ni = 0; ni < 4; ni++) {
                    int c0 = colbase + warpN * 32 + ni * 8 + 2 * qcol;
                    int c1 = c0 + 1;
                    if (c0 < C_CLS) {
                        s0 += __expf(S_SCALE * acc[mi][ni][0]);
                        s1 += __expf(S_SCALE * acc[mi][ni][2]);
                    }
                    if (c1 < C_CLS) {
                        s0 += __expf(S_SCALE * acc[mi][ni][1]);
                        s1 += __expf(S_SCALE * acc[mi][ni][3]);
                    }
                    #pragma unroll
                    for (int r = 0; r < 4; r++) acc[mi][ni][r] = 0.f;
                }
                s0 += __shfl_xor_sync(0xffffffffu, s0, 1);
                s0 += __shfl_xor_sync(0xffffffffu, s0, 2);
                s1 += __shfl_xor_sync(0xffffffffu, s1, 1);
                s1 += __shfl_xor_sync(0xffffffffu, s1, 2);
                if (qcol == 0) {
                    atomicAdd(g_rowsum + r0, s0);
                    atomicAdd(g_rowsum + r1, s1);
                }
            }
        }
    }
}

// ---------------- kernel 4: per-row loss + mean ----------------
__global__ __launch_bounds__(1024) void loss_kernel(float* __restrict__ out) {
    int b = threadIdx.x;
    float t = g_tgt[b];
    float tc = fminf(fmaxf(t, -1.0f + EPS_A), 1.0f - EPS_A);
    float num = S_SCALE * cosf(acosf(tc) + M_MARG);
    float excl = g_rowsum[b] - expf(S_SCALE * t);
    float denom = expf(num) + excl;
    float L = num - logf(denom);

    #pragma unroll
    for (int o = 16; o > 0; o >>= 1) L += __shfl_xor_sync(0xffffffffu, L, o);
    __shared__ float red[32];
    int w = threadIdx.x >> 5;
    if ((threadIdx.x & 31) == 0) red[w] = L;
    __syncthreads();
    if (w == 0) {
        float v = red[threadIdx.x & 31];
        #pragma unroll
        for (int o = 16; o > 0; o >>= 1) v += __shfl_xor_sync(0xffffffffu, v, o);
        if (threadIdx.x == 0) out[0] = -v / (float)B_ROWS;
    }
}

// ---------------- launch ----------------
extern "C" void kernel_launch(void* const* d_in, const int* in_sizes, int n_in,
                              void* d_out, int out_size) {
    const float* features = (const float*)d_in[0];
    const float* W        = (const float*)d_in[1];
    const void*  y_true   = d_in[2];
    float* out = (float*)d_out;

    cudaFuncSetAttribute(gemm_exp_kernel,
                         cudaFuncAttributeMaxDynamicSharedMemorySize, SMEM_BYTES);

    detect_kernel<<<1, 1>>>((const int*)y_true);
    wconv_kernel<<<50000, 256>>>(W);
    norm_kernel<<<B_ROWS, 128>>>(features);
    tgt_kernel<<<B_ROWS, 128>>>(W, y_true);
    const int grid = (C_CLS + BN - 1) / BN;  // 782
    gemm_exp_kernel<<<grid, 512, SMEM_BYTES>>>();
    loss_kernel<<<1, 1024>>>(out);
}